// round 10
// baseline (speedup 1.0000x reference)
#include <cuda_runtime.h>
#include <cuda_fp16.h>
#include <math.h>

#define NU 200000
#define NB 50000
#define NE 5000000
#define STRIDE_B 192
#define STRIDE_U 64

// ---------------- scratch ----------------
__device__ int g_cnt[NU + NB];
__device__ int g_bkt_ub[(size_t)NB * STRIDE_B];
__device__ int g_bkt_bu[(size_t)NU * STRIDE_U];

__device__ uint4 g_hs1_u[NU * 2];         // fp16 rows: 16 halves = 32B
__device__ uint4 g_hs1_b[NB * 2];
__device__ float g_ad1_u[NU];
__device__ float g_ad1_b[NB];
__device__ float g_hs2_u[NU * 2], g_hs2_b[NB * 2];
__device__ float g_ad2_u[NU];
__device__ float g_ad2_b[NB];

#define GB_BLOCKS ((NE / 8 + 255) / 256)
#define UBLK ((NU + 255) / 256)
#define BBLK ((NB + 255) / 256)

// ---------------- fused bucket build + layer-1 node transform ----------------
// __launch_bounds__(256, 6): cap regs ~42 so the latency-bound build branch
// runs at 75% occupancy (was 34% at 76 regs). Build processes one relation at
// a time to keep live registers under the cap; node branch may spill a little.
__global__ void __launch_bounds__(256, 6) build_node_kernel(
    const int* __restrict__ ub_src, const int* __restrict__ ub_dst,
    int* __restrict__ cnt_ub, int* __restrict__ bkt_ub,
    const int* __restrict__ bu_src, const int* __restrict__ bu_dst,
    int* __restrict__ cnt_bu, int* __restrict__ bkt_bu,
    const float* __restrict__ xu, const float* __restrict__ xb,
    const float* __restrict__ Ws_u, const float* __restrict__ Wd_u,
    const float* __restrict__ avd_u,
    const float* __restrict__ Ws_b, const float* __restrict__ Wd_b,
    const float* __restrict__ avd_b,
    uint4* __restrict__ hs_u, float* __restrict__ ad_u,
    uint4* __restrict__ hs_b, float* __restrict__ ad_b) {
    __shared__ float sWs[64 * 16], sWd[64 * 16], sad[16];

    if (blockIdx.x < GB_BLOCKS) {
        int t = blockIdx.x * 256 + threadIdx.x;
        if (t >= NE / 8) return;
        {   // relation ub (dst = badge)
            int4 d0 = ((const int4*)ub_dst)[2 * t + 0];
            int4 d1 = ((const int4*)ub_dst)[2 * t + 1];
            int4 s0 = ((const int4*)ub_src)[2 * t + 0];
            int4 s1 = ((const int4*)ub_src)[2 * t + 1];
            int r0 = atomicAdd(&cnt_ub[d0.x], 1);
            int r1 = atomicAdd(&cnt_ub[d0.y], 1);
            int r2 = atomicAdd(&cnt_ub[d0.z], 1);
            int r3 = atomicAdd(&cnt_ub[d0.w], 1);
            int r4 = atomicAdd(&cnt_ub[d1.x], 1);
            int r5 = atomicAdd(&cnt_ub[d1.y], 1);
            int r6 = atomicAdd(&cnt_ub[d1.z], 1);
            int r7 = atomicAdd(&cnt_ub[d1.w], 1);
            if (r0 < STRIDE_B) bkt_ub[(size_t)d0.x * STRIDE_B + r0] = s0.x;
            if (r1 < STRIDE_B) bkt_ub[(size_t)d0.y * STRIDE_B + r1] = s0.y;
            if (r2 < STRIDE_B) bkt_ub[(size_t)d0.z * STRIDE_B + r2] = s0.z;
            if (r3 < STRIDE_B) bkt_ub[(size_t)d0.w * STRIDE_B + r3] = s0.w;
            if (r4 < STRIDE_B) bkt_ub[(size_t)d1.x * STRIDE_B + r4] = s1.x;
            if (r5 < STRIDE_B) bkt_ub[(size_t)d1.y * STRIDE_B + r5] = s1.y;
            if (r6 < STRIDE_B) bkt_ub[(size_t)d1.z * STRIDE_B + r6] = s1.z;
            if (r7 < STRIDE_B) bkt_ub[(size_t)d1.w * STRIDE_B + r7] = s1.w;
        }
        {   // relation bu (dst = user)
            int4 d0 = ((const int4*)bu_dst)[2 * t + 0];
            int4 d1 = ((const int4*)bu_dst)[2 * t + 1];
            int4 s0 = ((const int4*)bu_src)[2 * t + 0];
            int4 s1 = ((const int4*)bu_src)[2 * t + 1];
            int q0 = atomicAdd(&cnt_bu[d0.x], 1);
            int q1 = atomicAdd(&cnt_bu[d0.y], 1);
            int q2 = atomicAdd(&cnt_bu[d0.z], 1);
            int q3 = atomicAdd(&cnt_bu[d0.w], 1);
            int q4 = atomicAdd(&cnt_bu[d1.x], 1);
            int q5 = atomicAdd(&cnt_bu[d1.y], 1);
            int q6 = atomicAdd(&cnt_bu[d1.z], 1);
            int q7 = atomicAdd(&cnt_bu[d1.w], 1);
            if (q0 < STRIDE_U) bkt_bu[(size_t)d0.x * STRIDE_U + q0] = s0.x;
            if (q1 < STRIDE_U) bkt_bu[(size_t)d0.y * STRIDE_U + q1] = s0.y;
            if (q2 < STRIDE_U) bkt_bu[(size_t)d0.z * STRIDE_U + q2] = s0.z;
            if (q3 < STRIDE_U) bkt_bu[(size_t)d0.w * STRIDE_U + q3] = s0.w;
            if (q4 < STRIDE_U) bkt_bu[(size_t)d1.x * STRIDE_U + q4] = s1.x;
            if (q5 < STRIDE_U) bkt_bu[(size_t)d1.y * STRIDE_U + q5] = s1.y;
            if (q6 < STRIDE_U) bkt_bu[(size_t)d1.z * STRIDE_U + q6] = s1.z;
            if (q7 < STRIDE_U) bkt_bu[(size_t)d1.w * STRIDE_U + q7] = s1.w;
        }
        return;
    }

    // ---------- node transform ----------
    int nb = blockIdx.x - GB_BLOCKS;
    bool isU = (nb < UBLK);
    const float* x   = isU ? xu : xb;
    const float* Ws  = isU ? Ws_u : Ws_b;
    const float* Wd  = isU ? Wd_u : Wd_b;
    const float* avd = isU ? avd_u : avd_b;
    uint4* hso       = isU ? hs_u : hs_b;
    float* ado       = isU ? ad_u : ad_b;
    int n            = isU ? NU : NB;
    int i = (isU ? nb : nb - UBLK) * 256 + threadIdx.x;

    for (int j = threadIdx.x; j < 1024; j += 256) { sWs[j] = Ws[j]; sWd[j] = Wd[j]; }
    if (threadIdx.x < 16) sad[threadIdx.x] = avd[threadIdx.x];
    __syncthreads();
    if (i >= n) return;

    float hs[16], hd[16];
#pragma unroll
    for (int c = 0; c < 16; c++) { hs[c] = 0.f; hd[c] = 0.f; }
    const float4* xp = (const float4*)(x + (size_t)i * 64);
#pragma unroll 4
    for (int q = 0; q < 16; q++) {
        float4 v = xp[q];
#pragma unroll
        for (int kk = 0; kk < 4; kk++) {
            float xk = (kk == 0) ? v.x : (kk == 1) ? v.y : (kk == 2) ? v.z : v.w;
            int k = q * 4 + kk;
#pragma unroll
            for (int c = 0; c < 16; c++) {
                hs[c] += xk * sWs[k * 16 + c];
                hd[c] += xk * sWd[k * 16 + c];
            }
        }
    }
    __half2 h2[8];
#pragma unroll
    for (int q = 0; q < 8; q++)
        h2[q] = __floats2half2_rn(hs[2 * q + 0], hs[2 * q + 1]);
    uint4 o0, o1;
    o0.x = *(unsigned int*)&h2[0]; o0.y = *(unsigned int*)&h2[1];
    o0.z = *(unsigned int*)&h2[2]; o0.w = *(unsigned int*)&h2[3];
    o1.x = *(unsigned int*)&h2[4]; o1.y = *(unsigned int*)&h2[5];
    o1.z = *(unsigned int*)&h2[6]; o1.w = *(unsigned int*)&h2[7];
    hso[(size_t)i * 2 + 0] = o0;
    hso[(size_t)i * 2 + 1] = o1;
    float ad = 0.f;
#pragma unroll
    for (int c = 0; c < 16; c++) ad += hd[c] * sad[c];
    ado[i] = ad;
}

// ---------------- layer-1 aggregation (per-lane gather) + fused L2 transform ----------
template <int G, int STRIDE>
__device__ __forceinline__ void agg1_grp(
    int g, int lane,
    const int* __restrict__ cnt, const int* __restrict__ bkt,
    const float* __restrict__ ad_, const uint4* __restrict__ hs,
    const float* __restrict__ avec, const float* __restrict__ bias,
    const float* __restrict__ W2s, const float* __restrict__ W2d,
    const float* __restrict__ a2d,
    float* __restrict__ hs2_out, float* __restrict__ ad2_out) {
    float a[16];
#pragma unroll
    for (int c = 0; c < 16; c++) a[c] = __ldg(&avec[c]);
    float adv = __ldg(&ad_[g]);
    int deg = __ldg(&cnt[g]);
    if (deg > STRIDE) deg = STRIDE;
    const int* row = bkt + (size_t)g * STRIDE;

    float s = 0.f;
    float acc[16];
#pragma unroll
    for (int c = 0; c < 16; c++) acc[c] = 0.f;

    int i = lane;
    int src = (i < deg) ? __ldg(&row[i]) : 0;
    while (i < deg) {
        int inext = i + G;
        int src_next = (inext < deg) ? __ldg(&row[inext]) : 0;
        uint4 v0 = __ldg(&hs[(size_t)src * 2 + 0]);
        uint4 v1 = __ldg(&hs[(size_t)src * 2 + 1]);
        unsigned int w32[8] = {v0.x, v0.y, v0.z, v0.w, v1.x, v1.y, v1.z, v1.w};
        float h[16];
#pragma unroll
        for (int q = 0; q < 8; q++) {
            float2 f = __half22float2(*(__half2*)&w32[q]);
            h[2 * q + 0] = f.x;
            h[2 * q + 1] = f.y;
        }
        float es = 0.f;
#pragma unroll
        for (int c = 0; c < 16; c++) es += h[c] * a[c];
        float e = es + adv;
        e = (e > 0.f) ? e : 0.2f * e;
        float w = __expf(e);
        s += w;
#pragma unroll
        for (int c = 0; c < 16; c++) acc[c] += w * h[c];
        src = src_next;
        i = inext;
    }

#pragma unroll
    for (int off = G / 2; off; off >>= 1) {
        s += __shfl_xor_sync(0xffffffffu, s, off);
#pragma unroll
        for (int c = 0; c < 16; c++)
            acc[c] += __shfl_xor_sync(0xffffffffu, acc[c], off);
    }

    if (lane == 0) {
        float inv = 1.0f / (s + 1e-16f);
        float s0 = 0.f, s1 = 0.f, d0 = 0.f, d1 = 0.f;
#pragma unroll
        for (int c = 0; c < 16; c++) {
            float h = fmaxf(acc[c] * inv + __ldg(&bias[c]), 0.f);
            s0 += h * __ldg(&W2s[c * 2 + 0]);
            s1 += h * __ldg(&W2s[c * 2 + 1]);
            d0 += h * __ldg(&W2d[c * 2 + 0]);
            d1 += h * __ldg(&W2d[c * 2 + 1]);
        }
        *(float2*)(hs2_out + (size_t)g * 2) = make_float2(s0, s1);
        ad2_out[g] = d0 * __ldg(&a2d[0]) + d1 * __ldg(&a2d[1]);
    }
}

__global__ void agg1_all(
    const int* __restrict__ cnt_ub, const int* __restrict__ bkt_ub,
    const float* __restrict__ ad1b, const uint4* __restrict__ hs1u,
    const float* __restrict__ a1ubs, const float* __restrict__ b1ub,
    const float* __restrict__ W2bus, const float* __restrict__ W2ubd,
    const float* __restrict__ a2ubd,
    float* __restrict__ hs2b, float* __restrict__ ad2b,
    const int* __restrict__ cnt_bu, const int* __restrict__ bkt_bu,
    const float* __restrict__ ad1u, const uint4* __restrict__ hs1b,
    const float* __restrict__ a1bus, const float* __restrict__ b1bu,
    const float* __restrict__ W2ubs, const float* __restrict__ W2bud,
    const float* __restrict__ a2bud,
    float* __restrict__ hs2u, float* __restrict__ ad2u) {
    int w = blockIdx.x * (blockDim.x >> 5) + (threadIdx.x >> 5);
    int wl = threadIdx.x & 31;
    if (w < NB) {
        agg1_grp<32, STRIDE_B>(w, wl, cnt_ub, bkt_ub, ad1b, hs1u, a1ubs, b1ub,
                               W2bus, W2ubd, a2ubd, hs2b, ad2b);
    } else {
        int g = (w - NB) * 4 + (wl >> 3);     // 4 user dsts per warp, G=8
        if (g < NU)
            agg1_grp<8, STRIDE_U>(g, wl & 7, cnt_bu, bkt_bu, ad1u, hs1b, a1bus, b1bu,
                                  W2ubs, W2bud, a2bud, hs2u, ad2u);
    }
}

// ---------------- layer-2 aggregation (merged relations) ----------------
template <int G, int STRIDE>
__device__ __forceinline__ void agg2_grp(int g, int lane,
                                         const int* __restrict__ cnt, const int* __restrict__ bkt,
                                         const float* __restrict__ ad_, const float* __restrict__ hs,
                                         const float* __restrict__ avec, const float* __restrict__ bias,
                                         float* __restrict__ out) {
    float a0 = __ldg(&avec[0]), a1 = __ldg(&avec[1]);
    float adv = __ldg(&ad_[g]);
    int deg = __ldg(&cnt[g]);
    if (deg > STRIDE) deg = STRIDE;
    const int* row = bkt + (size_t)g * STRIDE;

    float s = 0.f, acc0 = 0.f, acc1 = 0.f;
    int i = lane;
    int src = (i < deg) ? __ldg(&row[i]) : 0;
    while (i < deg) {
        int inext = i + G;
        int src_next = (inext < deg) ? __ldg(&row[inext]) : 0;
        float2 v = *(const float2*)(hs + (size_t)src * 2);
        float e = v.x * a0 + v.y * a1 + adv;
        e = (e > 0.f) ? e : 0.2f * e;
        float w = __expf(e);
        s += w;
        acc0 += w * v.x;
        acc1 += w * v.y;
        src = src_next;
        i = inext;
    }
#pragma unroll
    for (int off = G / 2; off; off >>= 1) {
        s    += __shfl_xor_sync(0xffffffffu, s, off);
        acc0 += __shfl_xor_sync(0xffffffffu, acc0, off);
        acc1 += __shfl_xor_sync(0xffffffffu, acc1, off);
    }
    if (lane == 0) {
        float inv = 1.0f / (s + 1e-16f);
        *(float2*)(out + (size_t)g * 2) =
            make_float2(acc0 * inv + __ldg(&bias[0]), acc1 * inv + __ldg(&bias[1]));
    }
}

__global__ void agg2_all(
    const int* __restrict__ cnt_ub, const int* __restrict__ bkt_ub,
    const float* __restrict__ ad2b, const float* __restrict__ hs2u,
    const float* __restrict__ a2ubs, const float* __restrict__ b2ub,
    float* __restrict__ out_b,
    const int* __restrict__ cnt_bu, const int* __restrict__ bkt_bu,
    const float* __restrict__ ad2u, const float* __restrict__ hs2b,
    const float* __restrict__ a2bus, const float* __restrict__ b2bu,
    float* __restrict__ out_u) {
    int w = blockIdx.x * (blockDim.x >> 5) + (threadIdx.x >> 5);
    int wl = threadIdx.x & 31;
    if (w < NB) {
        agg2_grp<32, STRIDE_B>(w, wl, cnt_ub, bkt_ub, ad2b, hs2u, a2ubs, b2ub, out_b);
    } else {
        int g = (w - NB) * 4 + (wl >> 3);
        if (g < NU)
            agg2_grp<8, STRIDE_U>(g, wl & 7, cnt_bu, bkt_bu, ad2u, hs2b, a2bus, b2bu, out_u);
    }
}

// ---------------- host ----------------
static void* sym_addr(const void* symbol) {
    void* p = nullptr;
    cudaGetSymbolAddress(&p, symbol);
    return p;
}

extern "C" void kernel_launch(void* const* d_in, const int* in_sizes, int n_in,
                              void* d_out, int out_size) {
    const float* x_user  = (const float*)d_in[0];
    const float* x_badge = (const float*)d_in[1];
    const int* ub_src = (const int*)d_in[2];
    const int* ub_dst = (const int*)d_in[3];
    const int* bu_src = (const int*)d_in[4];
    const int* bu_dst = (const int*)d_in[5];

    int iW1ubs = 8, iW1ubd = 9, ia1ubs = 10, ia1ubd = 11, ib1ub = 12;
    int iW1bus, iW1bud, ia1bus, ia1bud, ib1bu;
    int iW2ubs, iW2ubd, ia2ubs, ia2ubd, ib2ub;
    int iW2bus, iW2bud, ia2bus, ia2bud, ib2bu;
    if (in_sizes[13] == 1024) {
        iW1bus = 13; iW1bud = 14; ia1bus = 15; ia1bud = 16; ib1bu = 17;
        iW2ubs = 18; iW2ubd = 19; ia2ubs = 20; ia2ubd = 21; ib2ub = 22;
        iW2bus = 23; iW2bud = 24; ia2bus = 25; ia2bud = 26; ib2bu = 27;
    } else {
        iW2ubs = 13; iW2ubd = 14; ia2ubs = 15; ia2ubd = 16; ib2ub = 17;
        iW1bus = 18; iW1bud = 19; ia1bus = 20; ia1bud = 21; ib1bu = 22;
        iW2bus = 23; iW2bud = 24; ia2bus = 25; ia2bud = 26; ib2bu = 27;
    }
#define FP(i) ((const float*)d_in[i])

    int* cnt     = (int*)sym_addr(g_cnt);
    int* cnt_bu  = cnt;
    int* cnt_ub  = cnt + NU;
    int* bkt_ub  = (int*)sym_addr(g_bkt_ub);
    int* bkt_bu  = (int*)sym_addr(g_bkt_bu);
    uint4* hs1u = (uint4*)sym_addr(g_hs1_u);
    uint4* hs1b = (uint4*)sym_addr(g_hs1_b);
    float* ad1u = (float*)sym_addr(g_ad1_u);
    float* ad1b = (float*)sym_addr(g_ad1_b);
    float* hs2u = (float*)sym_addr(g_hs2_u);
    float* hs2b = (float*)sym_addr(g_hs2_b);
    float* ad2u = (float*)sym_addr(g_ad2_u);
    float* ad2b = (float*)sym_addr(g_ad2_b);

    // ---- bucket build + layer-1 node transforms (one fused launch) ----
    cudaMemsetAsync(cnt, 0, (NU + NB) * sizeof(int));
    build_node_kernel<<<GB_BLOCKS + UBLK + BBLK, 256>>>(
        ub_src, ub_dst, cnt_ub, bkt_ub,
        bu_src, bu_dst, cnt_bu, bkt_bu,
        x_user, x_badge,
        FP(iW1ubs), FP(iW1bud), FP(ia1bud),
        FP(iW1bus), FP(iW1ubd), FP(ia1ubd),
        hs1u, ad1u, hs1b, ad1b);

    // ---- layer 1 aggregation + fused layer-2 node transform (one launch) ----
    {
        long warps = (long)NB + (NU + 3) / 4;
        int blocks = (int)((warps * 32 + 255) / 256);
        agg1_all<<<blocks, 256>>>(
            cnt_ub, bkt_ub, ad1b, hs1u, FP(ia1ubs), FP(ib1ub),
            FP(iW2bus), FP(iW2ubd), FP(ia2ubd), hs2b, ad2b,
            cnt_bu, bkt_bu, ad1u, hs1b, FP(ia1bus), FP(ib1bu),
            FP(iW2ubs), FP(iW2bud), FP(ia2bud), hs2u, ad2u);
    }

    // ---- layer 2 aggregation -> outputs (one launch) ----
    float* out = (float*)d_out;   // [ou (200000x2) | ob (50000x2)]
    {
        long warps = (long)NB + (NU + 3) / 4;
        int blocks = (int)((warps * 32 + 255) / 256);
        agg2_all<<<blocks, 256>>>(
            cnt_ub, bkt_ub, ad2b, hs2u, FP(ia2ubs), FP(ib2ub), out + (size_t)NU * 2,
            cnt_bu, bkt_bu, ad2u, hs2b, FP(ia2bus), FP(ib2bu), out);
    }
}

// round 11
// speedup vs baseline: 1.3712x; 1.3712x over previous
#include <cuda_runtime.h>
#include <cuda_fp16.h>
#include <math.h>

#define NU 200000
#define NB 50000
#define NE 5000000
#define STRIDE_B 192
#define STRIDE_U 64

// ---------------- scratch ----------------
__device__ int g_cnt[NU + NB];
__device__ int g_bkt_ub[(size_t)NB * STRIDE_B];
__device__ int g_bkt_bu[(size_t)NU * STRIDE_U];

__device__ uint4 g_hs1_u[NU * 2];         // fp16 rows: 16 halves = 32B
__device__ uint4 g_hs1_b[NB * 2];
__device__ float g_ad1_u[NU];
__device__ float g_ad1_b[NB];
__device__ float g_hs2_u[NU * 2], g_hs2_b[NB * 2];
__device__ float g_ad2_u[NU];
__device__ float g_ad2_b[NB];

#define GB_BLOCKS ((NE / 8 + 255) / 256)
#define UBLK ((NU + 255) / 256)
#define BBLK ((NB + 255) / 256)

// ---------------- fused bucket build (round-9 exact) + slim node transform ----------
// Node branch uses ad = x @ (Wd @ avd): hd[16] accumulators eliminated ->
// node branch ~45 live regs, kernel max regs ~60, occupancy up WITHOUT a cap
// (round-10 showed forced caps spill and serialize; this is the algebraic fix).
__global__ void build_node_kernel(
    const int* __restrict__ ub_src, const int* __restrict__ ub_dst,
    int* __restrict__ cnt_ub, int* __restrict__ bkt_ub,
    const int* __restrict__ bu_src, const int* __restrict__ bu_dst,
    int* __restrict__ cnt_bu, int* __restrict__ bkt_bu,
    const float* __restrict__ xu, const float* __restrict__ xb,
    const float* __restrict__ Ws_u, const float* __restrict__ Wd_u,
    const float* __restrict__ avd_u,
    const float* __restrict__ Ws_b, const float* __restrict__ Wd_b,
    const float* __restrict__ avd_b,
    uint4* __restrict__ hs_u, float* __restrict__ ad_u,
    uint4* __restrict__ hs_b, float* __restrict__ ad_b) {
    __shared__ float sWs[64 * 16], swd[64];

    if (blockIdx.x < GB_BLOCKS) {
        // ---------- bucket build: both relations interleaved, 16 atomics in flight ----------
        int t = blockIdx.x * 256 + threadIdx.x;
        if (t >= NE / 8) return;
        int4 da0 = ((const int4*)ub_dst)[2 * t + 0];
        int4 da1 = ((const int4*)ub_dst)[2 * t + 1];
        int4 db0 = ((const int4*)bu_dst)[2 * t + 0];
        int4 db1 = ((const int4*)bu_dst)[2 * t + 1];
        int4 sa0 = ((const int4*)ub_src)[2 * t + 0];
        int4 sa1 = ((const int4*)ub_src)[2 * t + 1];
        int4 sb0 = ((const int4*)bu_src)[2 * t + 0];
        int4 sb1 = ((const int4*)bu_src)[2 * t + 1];

        int r0 = atomicAdd(&cnt_ub[da0.x], 1);
        int r1 = atomicAdd(&cnt_ub[da0.y], 1);
        int r2 = atomicAdd(&cnt_ub[da0.z], 1);
        int r3 = atomicAdd(&cnt_ub[da0.w], 1);
        int r4 = atomicAdd(&cnt_ub[da1.x], 1);
        int r5 = atomicAdd(&cnt_ub[da1.y], 1);
        int r6 = atomicAdd(&cnt_ub[da1.z], 1);
        int r7 = atomicAdd(&cnt_ub[da1.w], 1);
        int q0 = atomicAdd(&cnt_bu[db0.x], 1);
        int q1 = atomicAdd(&cnt_bu[db0.y], 1);
        int q2 = atomicAdd(&cnt_bu[db0.z], 1);
        int q3 = atomicAdd(&cnt_bu[db0.w], 1);
        int q4 = atomicAdd(&cnt_bu[db1.x], 1);
        int q5 = atomicAdd(&cnt_bu[db1.y], 1);
        int q6 = atomicAdd(&cnt_bu[db1.z], 1);
        int q7 = atomicAdd(&cnt_bu[db1.w], 1);

        if (r0 < STRIDE_B) bkt_ub[(size_t)da0.x * STRIDE_B + r0] = sa0.x;
        if (r1 < STRIDE_B) bkt_ub[(size_t)da0.y * STRIDE_B + r1] = sa0.y;
        if (r2 < STRIDE_B) bkt_ub[(size_t)da0.z * STRIDE_B + r2] = sa0.z;
        if (r3 < STRIDE_B) bkt_ub[(size_t)da0.w * STRIDE_B + r3] = sa0.w;
        if (r4 < STRIDE_B) bkt_ub[(size_t)da1.x * STRIDE_B + r4] = sa1.x;
        if (r5 < STRIDE_B) bkt_ub[(size_t)da1.y * STRIDE_B + r5] = sa1.y;
        if (r6 < STRIDE_B) bkt_ub[(size_t)da1.z * STRIDE_B + r6] = sa1.z;
        if (r7 < STRIDE_B) bkt_ub[(size_t)da1.w * STRIDE_B + r7] = sa1.w;
        if (q0 < STRIDE_U) bkt_bu[(size_t)db0.x * STRIDE_U + q0] = sb0.x;
        if (q1 < STRIDE_U) bkt_bu[(size_t)db0.y * STRIDE_U + q1] = sb0.y;
        if (q2 < STRIDE_U) bkt_bu[(size_t)db0.z * STRIDE_U + q2] = sb0.z;
        if (q3 < STRIDE_U) bkt_bu[(size_t)db0.w * STRIDE_U + q3] = sb0.w;
        if (q4 < STRIDE_U) bkt_bu[(size_t)db1.x * STRIDE_U + q4] = sb1.x;
        if (q5 < STRIDE_U) bkt_bu[(size_t)db1.y * STRIDE_U + q5] = sb1.y;
        if (q6 < STRIDE_U) bkt_bu[(size_t)db1.z * STRIDE_U + q6] = sb1.z;
        if (q7 < STRIDE_U) bkt_bu[(size_t)db1.w * STRIDE_U + q7] = sb1.w;
        return;
    }

    // ---------- node transform (hd eliminated via wdvec = Wd @ avd) ----------
    int nb = blockIdx.x - GB_BLOCKS;
    bool isU = (nb < UBLK);
    const float* x   = isU ? xu : xb;
    const float* Ws  = isU ? Ws_u : Ws_b;
    const float* Wd  = isU ? Wd_u : Wd_b;
    const float* avd = isU ? avd_u : avd_b;
    uint4* hso       = isU ? hs_u : hs_b;
    float* ado       = isU ? ad_u : ad_b;
    int n            = isU ? NU : NB;
    int i = (isU ? nb : nb - UBLK) * 256 + threadIdx.x;

    for (int j = threadIdx.x; j < 1024; j += 256) sWs[j] = Ws[j];
    if (threadIdx.x < 64) {
        float acc = 0.f;
#pragma unroll
        for (int c = 0; c < 16; c++) acc += Wd[threadIdx.x * 16 + c] * avd[c];
        swd[threadIdx.x] = acc;
    }
    __syncthreads();
    if (i >= n) return;

    float hs[16];
#pragma unroll
    for (int c = 0; c < 16; c++) hs[c] = 0.f;
    float ad = 0.f;
    const float4* xp = (const float4*)(x + (size_t)i * 64);
#pragma unroll 4
    for (int q = 0; q < 16; q++) {
        float4 v = xp[q];
#pragma unroll
        for (int kk = 0; kk < 4; kk++) {
            float xk = (kk == 0) ? v.x : (kk == 1) ? v.y : (kk == 2) ? v.z : v.w;
            int k = q * 4 + kk;
#pragma unroll
            for (int c = 0; c < 16; c++) hs[c] += xk * sWs[k * 16 + c];
            ad += xk * swd[k];
        }
    }
    __half2 h2[8];
#pragma unroll
    for (int q = 0; q < 8; q++)
        h2[q] = __floats2half2_rn(hs[2 * q + 0], hs[2 * q + 1]);
    uint4 o0, o1;
    o0.x = *(unsigned int*)&h2[0]; o0.y = *(unsigned int*)&h2[1];
    o0.z = *(unsigned int*)&h2[2]; o0.w = *(unsigned int*)&h2[3];
    o1.x = *(unsigned int*)&h2[4]; o1.y = *(unsigned int*)&h2[5];
    o1.z = *(unsigned int*)&h2[6]; o1.w = *(unsigned int*)&h2[7];
    hso[(size_t)i * 2 + 0] = o0;
    hso[(size_t)i * 2 + 1] = o1;
    ado[i] = ad;
}

// ---------------- layer-1 aggregation (per-lane gather) + fused L2 transform ----------
template <int G, int STRIDE>
__device__ __forceinline__ void agg1_grp(
    int g, int lane,
    const int* __restrict__ cnt, const int* __restrict__ bkt,
    const float* __restrict__ ad_, const uint4* __restrict__ hs,
    const float* __restrict__ avec, const float* __restrict__ bias,
    const float* __restrict__ W2s, const float* __restrict__ W2d,
    const float* __restrict__ a2d,
    float* __restrict__ hs2_out, float* __restrict__ ad2_out) {
    float a[16];
#pragma unroll
    for (int c = 0; c < 16; c++) a[c] = __ldg(&avec[c]);
    float adv = __ldg(&ad_[g]);
    int deg = __ldg(&cnt[g]);
    if (deg > STRIDE) deg = STRIDE;
    const int* row = bkt + (size_t)g * STRIDE;

    float s = 0.f;
    float acc[16];
#pragma unroll
    for (int c = 0; c < 16; c++) acc[c] = 0.f;

    int i = lane;
    int src = (i < deg) ? __ldg(&row[i]) : 0;
    while (i < deg) {
        int inext = i + G;
        int src_next = (inext < deg) ? __ldg(&row[inext]) : 0;
        uint4 v0 = __ldg(&hs[(size_t)src * 2 + 0]);
        uint4 v1 = __ldg(&hs[(size_t)src * 2 + 1]);
        unsigned int w32[8] = {v0.x, v0.y, v0.z, v0.w, v1.x, v1.y, v1.z, v1.w};
        float h[16];
#pragma unroll
        for (int q = 0; q < 8; q++) {
            float2 f = __half22float2(*(__half2*)&w32[q]);
            h[2 * q + 0] = f.x;
            h[2 * q + 1] = f.y;
        }
        float es = 0.f;
#pragma unroll
        for (int c = 0; c < 16; c++) es += h[c] * a[c];
        float e = es + adv;
        e = (e > 0.f) ? e : 0.2f * e;
        float w = __expf(e);
        s += w;
#pragma unroll
        for (int c = 0; c < 16; c++) acc[c] += w * h[c];
        src = src_next;
        i = inext;
    }

#pragma unroll
    for (int off = G / 2; off; off >>= 1) {
        s += __shfl_xor_sync(0xffffffffu, s, off);
#pragma unroll
        for (int c = 0; c < 16; c++)
            acc[c] += __shfl_xor_sync(0xffffffffu, acc[c], off);
    }

    if (lane == 0) {
        float inv = 1.0f / (s + 1e-16f);
        float s0 = 0.f, s1 = 0.f, d0 = 0.f, d1 = 0.f;
#pragma unroll
        for (int c = 0; c < 16; c++) {
            float h = fmaxf(acc[c] * inv + __ldg(&bias[c]), 0.f);
            s0 += h * __ldg(&W2s[c * 2 + 0]);
            s1 += h * __ldg(&W2s[c * 2 + 1]);
            d0 += h * __ldg(&W2d[c * 2 + 0]);
            d1 += h * __ldg(&W2d[c * 2 + 1]);
        }
        *(float2*)(hs2_out + (size_t)g * 2) = make_float2(s0, s1);
        ad2_out[g] = d0 * __ldg(&a2d[0]) + d1 * __ldg(&a2d[1]);
    }
}

__global__ void agg1_all(
    const int* __restrict__ cnt_ub, const int* __restrict__ bkt_ub,
    const float* __restrict__ ad1b, const uint4* __restrict__ hs1u,
    const float* __restrict__ a1ubs, const float* __restrict__ b1ub,
    const float* __restrict__ W2bus, const float* __restrict__ W2ubd,
    const float* __restrict__ a2ubd,
    float* __restrict__ hs2b, float* __restrict__ ad2b,
    const int* __restrict__ cnt_bu, const int* __restrict__ bkt_bu,
    const float* __restrict__ ad1u, const uint4* __restrict__ hs1b,
    const float* __restrict__ a1bus, const float* __restrict__ b1bu,
    const float* __restrict__ W2ubs, const float* __restrict__ W2bud,
    const float* __restrict__ a2bud,
    float* __restrict__ hs2u, float* __restrict__ ad2u) {
    int w = blockIdx.x * (blockDim.x >> 5) + (threadIdx.x >> 5);
    int wl = threadIdx.x & 31;
    if (w < NB) {
        agg1_grp<32, STRIDE_B>(w, wl, cnt_ub, bkt_ub, ad1b, hs1u, a1ubs, b1ub,
                               W2bus, W2ubd, a2ubd, hs2b, ad2b);
    } else {
        int g = (w - NB) * 4 + (wl >> 3);     // 4 user dsts per warp, G=8
        if (g < NU)
            agg1_grp<8, STRIDE_U>(g, wl & 7, cnt_bu, bkt_bu, ad1u, hs1b, a1bus, b1bu,
                                  W2ubs, W2bud, a2bud, hs2u, ad2u);
    }
}

// ---------------- layer-2 aggregation (merged relations) ----------------
template <int G, int STRIDE>
__device__ __forceinline__ void agg2_grp(int g, int lane,
                                         const int* __restrict__ cnt, const int* __restrict__ bkt,
                                         const float* __restrict__ ad_, const float* __restrict__ hs,
                                         const float* __restrict__ avec, const float* __restrict__ bias,
                                         float* __restrict__ out) {
    float a0 = __ldg(&avec[0]), a1 = __ldg(&avec[1]);
    float adv = __ldg(&ad_[g]);
    int deg = __ldg(&cnt[g]);
    if (deg > STRIDE) deg = STRIDE;
    const int* row = bkt + (size_t)g * STRIDE;

    float s = 0.f, acc0 = 0.f, acc1 = 0.f;
    int i = lane;
    int src = (i < deg) ? __ldg(&row[i]) : 0;
    while (i < deg) {
        int inext = i + G;
        int src_next = (inext < deg) ? __ldg(&row[inext]) : 0;
        float2 v = *(const float2*)(hs + (size_t)src * 2);
        float e = v.x * a0 + v.y * a1 + adv;
        e = (e > 0.f) ? e : 0.2f * e;
        float w = __expf(e);
        s += w;
        acc0 += w * v.x;
        acc1 += w * v.y;
        src = src_next;
        i = inext;
    }
#pragma unroll
    for (int off = G / 2; off; off >>= 1) {
        s    += __shfl_xor_sync(0xffffffffu, s, off);
        acc0 += __shfl_xor_sync(0xffffffffu, acc0, off);
        acc1 += __shfl_xor_sync(0xffffffffu, acc1, off);
    }
    if (lane == 0) {
        float inv = 1.0f / (s + 1e-16f);
        *(float2*)(out + (size_t)g * 2) =
            make_float2(acc0 * inv + __ldg(&bias[0]), acc1 * inv + __ldg(&bias[1]));
    }
}

__global__ void agg2_all(
    const int* __restrict__ cnt_ub, const int* __restrict__ bkt_ub,
    const float* __restrict__ ad2b, const float* __restrict__ hs2u,
    const float* __restrict__ a2ubs, const float* __restrict__ b2ub,
    float* __restrict__ out_b,
    const int* __restrict__ cnt_bu, const int* __restrict__ bkt_bu,
    const float* __restrict__ ad2u, const float* __restrict__ hs2b,
    const float* __restrict__ a2bus, const float* __restrict__ b2bu,
    float* __restrict__ out_u) {
    int w = blockIdx.x * (blockDim.x >> 5) + (threadIdx.x >> 5);
    int wl = threadIdx.x & 31;
    if (w < NB) {
        agg2_grp<32, STRIDE_B>(w, wl, cnt_ub, bkt_ub, ad2b, hs2u, a2ubs, b2ub, out_b);
    } else {
        int g = (w - NB) * 4 + (wl >> 3);
        if (g < NU)
            agg2_grp<8, STRIDE_U>(g, wl & 7, cnt_bu, bkt_bu, ad2u, hs2b, a2bus, b2bu, out_u);
    }
}

// ---------------- host ----------------
static void* sym_addr(const void* symbol) {
    void* p = nullptr;
    cudaGetSymbolAddress(&p, symbol);
    return p;
}

extern "C" void kernel_launch(void* const* d_in, const int* in_sizes, int n_in,
                              void* d_out, int out_size) {
    const float* x_user  = (const float*)d_in[0];
    const float* x_badge = (const float*)d_in[1];
    const int* ub_src = (const int*)d_in[2];
    const int* ub_dst = (const int*)d_in[3];
    const int* bu_src = (const int*)d_in[4];
    const int* bu_dst = (const int*)d_in[5];

    int iW1ubs = 8, iW1ubd = 9, ia1ubs = 10, ia1ubd = 11, ib1ub = 12;
    int iW1bus, iW1bud, ia1bus, ia1bud, ib1bu;
    int iW2ubs, iW2ubd, ia2ubs, ia2ubd, ib2ub;
    int iW2bus, iW2bud, ia2bus, ia2bud, ib2bu;
    if (in_sizes[13] == 1024) {
        iW1bus = 13; iW1bud = 14; ia1bus = 15; ia1bud = 16; ib1bu = 17;
        iW2ubs = 18; iW2ubd = 19; ia2ubs = 20; ia2ubd = 21; ib2ub = 22;
        iW2bus = 23; iW2bud = 24; ia2bus = 25; ia2bud = 26; ib2bu = 27;
    } else {
        iW2ubs = 13; iW2ubd = 14; ia2ubs = 15; ia2ubd = 16; ib2ub = 17;
        iW1bus = 18; iW1bud = 19; ia1bus = 20; ia1bud = 21; ib1bu = 22;
        iW2bus = 23; iW2bud = 24; ia2bus = 25; ia2bud = 26; ib2bu = 27;
    }
#define FP(i) ((const float*)d_in[i])

    int* cnt     = (int*)sym_addr(g_cnt);
    int* cnt_bu  = cnt;
    int* cnt_ub  = cnt + NU;
    int* bkt_ub  = (int*)sym_addr(g_bkt_ub);
    int* bkt_bu  = (int*)sym_addr(g_bkt_bu);
    uint4* hs1u = (uint4*)sym_addr(g_hs1_u);
    uint4* hs1b = (uint4*)sym_addr(g_hs1_b);
    float* ad1u = (float*)sym_addr(g_ad1_u);
    float* ad1b = (float*)sym_addr(g_ad1_b);
    float* hs2u = (float*)sym_addr(g_hs2_u);
    float* hs2b = (float*)sym_addr(g_hs2_b);
    float* ad2u = (float*)sym_addr(g_ad2_u);
    float* ad2b = (float*)sym_addr(g_ad2_b);

    // ---- bucket build + layer-1 node transforms (one fused launch) ----
    cudaMemsetAsync(cnt, 0, (NU + NB) * sizeof(int));
    build_node_kernel<<<GB_BLOCKS + UBLK + BBLK, 256>>>(
        ub_src, ub_dst, cnt_ub, bkt_ub,
        bu_src, bu_dst, cnt_bu, bkt_bu,
        x_user, x_badge,
        FP(iW1ubs), FP(iW1bud), FP(ia1bud),
        FP(iW1bus), FP(iW1ubd), FP(ia1ubd),
        hs1u, ad1u, hs1b, ad1b);

    // ---- layer 1 aggregation + fused layer-2 node transform (one launch) ----
    {
        long warps = (long)NB + (NU + 3) / 4;
        int blocks = (int)((warps * 32 + 255) / 256);
        agg1_all<<<blocks, 256>>>(
            cnt_ub, bkt_ub, ad1b, hs1u, FP(ia1ubs), FP(ib1ub),
            FP(iW2bus), FP(iW2ubd), FP(ia2ubd), hs2b, ad2b,
            cnt_bu, bkt_bu, ad1u, hs1b, FP(ia1bus), FP(ib1bu),
            FP(iW2ubs), FP(iW2bud), FP(ia2bud), hs2u, ad2u);
    }

    // ---- layer 2 aggregation -> outputs (one launch) ----
    float* out = (float*)d_out;   // [ou (200000x2) | ob (50000x2)]
    {
        long warps = (long)NB + (NU + 3) / 4;
        int blocks = (int)((warps * 32 + 255) / 256);
        agg2_all<<<blocks, 256>>>(
            cnt_ub, bkt_ub, ad2b, hs2u, FP(ia2ubs), FP(ib2ub), out + (size_t)NU * 2,
            cnt_bu, bkt_bu, ad2u, hs2b, FP(ia2bus), FP(ib2bu), out);
    }
}